// round 1
// baseline (speedup 1.0000x reference)
#include <cuda_runtime.h>
#include <math.h>

// Problem constants
#define BB 2
#define SS 2048
#define DD 1024
#define HH 16
#define DHK 64
#define MTOT (BB*SS)          // 4096 rows

// ---------------------------------------------------------------------------
// Scratch (device globals; no allocation allowed)
// ---------------------------------------------------------------------------
__device__ float g_Q[MTOT * DD];
__device__ float g_K[MTOT * DD];
__device__ float g_V[MTOT * DD];
__device__ float g_O[MTOT * DD];
__device__ float g_T[MTOT * DD];
__device__ float g_R[MTOT * DD];
__device__ float g_Hm[MTOT * (DD/2)];

// ---------------------------------------------------------------------------
// SGEMM: C[M,N] = A[M,K] @ W[K,N] + bias, optional ReLU.
// 128x128 block tile, K-tile 8, 256 threads, 8x8 per thread (4+4 split).
// Requires M%128==0, N%128==0, K%8==0.
// ---------------------------------------------------------------------------
template<int RELU>
__global__ __launch_bounds__(256) void sgemm_bias(
    const float* __restrict__ A, const float* __restrict__ W,
    const float* __restrict__ bias, float* __restrict__ C,
    int M, int N, int K)
{
    __shared__ float As[8][128];
    __shared__ float Ws[8][128];

    const int tid = threadIdx.x;
    const int tx = tid & 15;
    const int ty = tid >> 4;
    const int rowBase = blockIdx.y * 128;
    const int colBase = blockIdx.x * 128;

    const int aRow = tid >> 1;            // 0..127
    const int aCol = (tid & 1) * 4;       // 0 or 4
    const int wRow = tid >> 5;            // 0..7
    const int wCol = (tid & 31) * 4;      // 0..124

    const float* Ag = A + (size_t)(rowBase + aRow) * K + aCol;
    const float* Wg = W + (size_t)wRow * N + colBase + wCol;

    float acc[8][8];
    #pragma unroll
    for (int i = 0; i < 8; i++)
        #pragma unroll
        for (int j = 0; j < 8; j++) acc[i][j] = 0.0f;

    for (int k0 = 0; k0 < K; k0 += 8) {
        float4 av = *(const float4*)(Ag + k0);
        float4 wv = *(const float4*)(Wg + (size_t)k0 * N);
        __syncthreads();
        As[aCol + 0][aRow] = av.x;
        As[aCol + 1][aRow] = av.y;
        As[aCol + 2][aRow] = av.z;
        As[aCol + 3][aRow] = av.w;
        *(float4*)&Ws[wRow][wCol] = wv;
        __syncthreads();
        #pragma unroll
        for (int kk = 0; kk < 8; kk++) {
            float a[8], b[8];
            float4 t;
            t = *(float4*)&As[kk][ty * 4];       a[0]=t.x; a[1]=t.y; a[2]=t.z; a[3]=t.w;
            t = *(float4*)&As[kk][64 + ty * 4];  a[4]=t.x; a[5]=t.y; a[6]=t.z; a[7]=t.w;
            t = *(float4*)&Ws[kk][tx * 4];       b[0]=t.x; b[1]=t.y; b[2]=t.z; b[3]=t.w;
            t = *(float4*)&Ws[kk][64 + tx * 4];  b[4]=t.x; b[5]=t.y; b[6]=t.z; b[7]=t.w;
            #pragma unroll
            for (int i = 0; i < 8; i++)
                #pragma unroll
                for (int j = 0; j < 8; j++)
                    acc[i][j] = fmaf(a[i], b[j], acc[i][j]);
        }
    }

    // Epilogue
    float bcol[8];
    const float* bptr = bias + colBase;
    #pragma unroll
    for (int j = 0; j < 4; j++) {
        bcol[j]     = bptr[tx * 4 + j];
        bcol[4 + j] = bptr[64 + tx * 4 + j];
    }
    #pragma unroll
    for (int i = 0; i < 8; i++) {
        int row = rowBase + ((i < 4) ? (ty * 4 + i) : (64 + ty * 4 + (i - 4)));
        float* Cp = C + (size_t)row * N + colBase;
        float4 v0, v1;
        float o[8];
        #pragma unroll
        for (int j = 0; j < 8; j++) {
            float v = acc[i][j] + bcol[j];
            if (RELU) v = fmaxf(v, 0.0f);
            o[j] = v;
        }
        v0.x=o[0]; v0.y=o[1]; v0.z=o[2]; v0.w=o[3];
        v1.x=o[4]; v1.y=o[5]; v1.z=o[6]; v1.w=o[7];
        *(float4*)(Cp + tx * 4)      = v0;
        *(float4*)(Cp + 64 + tx * 4) = v1;
    }
}

// ---------------------------------------------------------------------------
// Fused flash attention, fp32. Grid: (S/64, H, B), 256 threads.
// 64 query rows per block, loop over 32 key tiles of 64, online softmax.
// Layouts: Q/K/V/O are [(b*S + s), H*64] row-major.
// scale = 1/sqrt(D_model) = 1/32 (as in reference source).
// ---------------------------------------------------------------------------
#define LDP 68                        // padded smem row (floats)
#define ATTN_SMEM (4*64*LDP*4 + 64*4) // Qs,Ks,Vs,Ps + mask = 69888 B

__global__ __launch_bounds__(256) void attn_kernel(
    const float* __restrict__ Q, const float* __restrict__ K,
    const float* __restrict__ V, const float* __restrict__ mask,
    float* __restrict__ O)
{
    extern __shared__ float sm[];
    float* Qs = sm;
    float* Ks = Qs + 64 * LDP;
    float* Vs = Ks + 64 * LDP;
    float* Ps = Vs + 64 * LDP;
    float* mk = Ps + 64 * LDP;

    const int tid = threadIdx.x;
    const int tx = tid & 15;
    const int ty = tid >> 4;
    const int b  = blockIdx.z;
    const int h  = blockIdx.y;
    const int q0 = blockIdx.x * 64;
    const float scale = 0.03125f;   // 1/sqrt(1024)

    const float* Qg = Q + ((size_t)(b * SS + q0)) * DD + h * DHK;
    const float* Kg = K + ((size_t)b * SS) * DD + h * DHK;
    const float* Vg = V + ((size_t)b * SS) * DD + h * DHK;

    // Load + pre-scale Q tile
    {
        int col = (tid & 15) * 4;
        #pragma unroll
        for (int r = 0; r < 4; r++) {
            int row = r * 16 + (tid >> 4);
            float4 v = *(const float4*)(Qg + (size_t)row * DD + col);
            float* dst = &Qs[row * LDP + col];
            dst[0] = v.x * scale; dst[1] = v.y * scale;
            dst[2] = v.z * scale; dst[3] = v.w * scale;
        }
    }

    float acc[4][4];
    float mrow[4], lrow[4];
    #pragma unroll
    for (int i = 0; i < 4; i++) {
        mrow[i] = -INFINITY; lrow[i] = 0.0f;
        #pragma unroll
        for (int j = 0; j < 4; j++) acc[i][j] = 0.0f;
    }

    for (int kt = 0; kt < SS / 64; kt++) {
        const int k0 = kt * 64;
        __syncthreads();   // prev-iter Ks/Vs/Ps fully consumed (also covers Qs on iter 0)
        {
            int col = (tid & 15) * 4;
            #pragma unroll
            for (int r = 0; r < 4; r++) {
                int row = r * 16 + (tid >> 4);
                float4 kv = *(const float4*)(Kg + (size_t)(k0 + row) * DD + col);
                float4 vv = *(const float4*)(Vg + (size_t)(k0 + row) * DD + col);
                *(float4*)&Ks[row * LDP + col] = kv;
                *(float4*)&Vs[row * LDP + col] = vv;
            }
            if (tid < 64) mk[tid] = (mask[b * SS + k0 + tid] - 1.0f) * 1e12f;
        }
        __syncthreads();

        // s = Qs @ Ks^T  (rows ty*4+i, cols tx*4+j)
        float s[4][4];
        #pragma unroll
        for (int i = 0; i < 4; i++)
            #pragma unroll
            for (int j = 0; j < 4; j++) s[i][j] = 0.0f;

        #pragma unroll 4
        for (int d4 = 0; d4 < 16; d4++) {
            float4 qv[4], kv[4];
            #pragma unroll
            for (int i = 0; i < 4; i++) qv[i] = *(float4*)&Qs[(ty * 4 + i) * LDP + d4 * 4];
            #pragma unroll
            for (int j = 0; j < 4; j++) kv[j] = *(float4*)&Ks[(tx * 4 + j) * LDP + d4 * 4];
            #pragma unroll
            for (int i = 0; i < 4; i++)
                #pragma unroll
                for (int j = 0; j < 4; j++) {
                    s[i][j] = fmaf(qv[i].x, kv[j].x, s[i][j]);
                    s[i][j] = fmaf(qv[i].y, kv[j].y, s[i][j]);
                    s[i][j] = fmaf(qv[i].z, kv[j].z, s[i][j]);
                    s[i][j] = fmaf(qv[i].w, kv[j].w, s[i][j]);
                }
        }
        // mask
        {
            float mj[4];
            #pragma unroll
            for (int j = 0; j < 4; j++) mj[j] = mk[tx * 4 + j];
            #pragma unroll
            for (int i = 0; i < 4; i++)
                #pragma unroll
                for (int j = 0; j < 4; j++) s[i][j] += mj[j];
        }

        // Online softmax update
        float tmax[4];
        #pragma unroll
        for (int i = 0; i < 4; i++)
            tmax[i] = fmaxf(fmaxf(s[i][0], s[i][1]), fmaxf(s[i][2], s[i][3]));
        #pragma unroll
        for (int o = 8; o >= 1; o >>= 1)
            #pragma unroll
            for (int i = 0; i < 4; i++)
                tmax[i] = fmaxf(tmax[i], __shfl_xor_sync(0xffffffffu, tmax[i], o));

        float p[4][4], corr[4], part[4];
        #pragma unroll
        for (int i = 0; i < 4; i++) {
            float mn = fmaxf(mrow[i], tmax[i]);
            corr[i] = __expf(mrow[i] - mn);
            mrow[i] = mn;
            float ps = 0.0f;
            #pragma unroll
            for (int j = 0; j < 4; j++) {
                p[i][j] = __expf(s[i][j] - mn);
                ps += p[i][j];
            }
            part[i] = ps;
        }
        #pragma unroll
        for (int o = 8; o >= 1; o >>= 1)
            #pragma unroll
            for (int i = 0; i < 4; i++)
                part[i] += __shfl_xor_sync(0xffffffffu, part[i], o);
        #pragma unroll
        for (int i = 0; i < 4; i++) {
            lrow[i] = lrow[i] * corr[i] + part[i];
            #pragma unroll
            for (int j = 0; j < 4; j++) acc[i][j] *= corr[i];
        }

        // Store P tile
        #pragma unroll
        for (int i = 0; i < 4; i++) {
            float4 pv; pv.x = p[i][0]; pv.y = p[i][1]; pv.z = p[i][2]; pv.w = p[i][3];
            *(float4*)&Ps[(ty * 4 + i) * LDP + tx * 4] = pv;
        }
        __syncthreads();

        // acc += P @ V
        #pragma unroll 4
        for (int k4 = 0; k4 < 16; k4++) {
            float4 pv[4], vv[4];
            #pragma unroll
            for (int i = 0; i < 4; i++)  pv[i] = *(float4*)&Ps[(ty * 4 + i) * LDP + k4 * 4];
            #pragma unroll
            for (int kk = 0; kk < 4; kk++) vv[kk] = *(float4*)&Vs[(k4 * 4 + kk) * LDP + tx * 4];
            #pragma unroll
            for (int i = 0; i < 4; i++) {
                const float* pf = (const float*)&pv[i];
                #pragma unroll
                for (int kk = 0; kk < 4; kk++) {
                    const float* vf = (const float*)&vv[kk];
                    float pk = pf[kk];
                    acc[i][0] = fmaf(pk, vf[0], acc[i][0]);
                    acc[i][1] = fmaf(pk, vf[1], acc[i][1]);
                    acc[i][2] = fmaf(pk, vf[2], acc[i][2]);
                    acc[i][3] = fmaf(pk, vf[3], acc[i][3]);
                }
            }
        }
    }

    // Write output
    float* Og = O + ((size_t)(b * SS + q0)) * DD + h * DHK;
    #pragma unroll
    for (int i = 0; i < 4; i++) {
        float inv = 1.0f / lrow[i];
        int row = ty * 4 + i;
        float4 o;
        o.x = acc[i][0] * inv; o.y = acc[i][1] * inv;
        o.z = acc[i][2] * inv; o.w = acc[i][3] * inv;
        *(float4*)(Og + (size_t)row * DD + tx * 4) = o;
    }
}

// ---------------------------------------------------------------------------
// Residual add + RMSNorm: out = gamma * x / (rms + eps), x = a + b,
// rms = sqrt(mean(x^2)). One block per row (D=1024, 256 thr x float4).
// ---------------------------------------------------------------------------
__global__ __launch_bounds__(256) void add_rmsnorm(
    const float* __restrict__ a, const float* __restrict__ b,
    const float* __restrict__ gamma, float* __restrict__ out)
{
    const int row = blockIdx.x;
    const int t = threadIdx.x;
    const float4* pa = (const float4*)(a + (size_t)row * DD);
    const float4* pb = (const float4*)(b + (size_t)row * DD);
    float4 xa = pa[t], xb = pb[t];
    float4 x;
    x.x = xa.x + xb.x; x.y = xa.y + xb.y; x.z = xa.z + xb.z; x.w = xa.w + xb.w;
    float ss = x.x * x.x + x.y * x.y + x.z * x.z + x.w * x.w;
    #pragma unroll
    for (int o = 16; o >= 1; o >>= 1)
        ss += __shfl_xor_sync(0xffffffffu, ss, o);
    __shared__ float red[8];
    if ((t & 31) == 0) red[t >> 5] = ss;
    __syncthreads();
    float tot = red[0] + red[1] + red[2] + red[3] + red[4] + red[5] + red[6] + red[7];
    float rms = sqrtf(tot * (1.0f / 1024.0f));
    float inv = 1.0f / (rms + 1e-8f);
    float4 gv = ((const float4*)gamma)[t];
    float4 o;
    o.x = gv.x * x.x * inv; o.y = gv.y * x.y * inv;
    o.z = gv.z * x.z * inv; o.w = gv.w * x.w * inv;
    ((float4*)(out + (size_t)row * DD))[t] = o;
}

// ---------------------------------------------------------------------------
// Launch
// ---------------------------------------------------------------------------
extern "C" void kernel_launch(void* const* d_in, const int* in_sizes, int n_in,
                              void* d_out, int out_size)
{
    const float* query = (const float*)d_in[0];
    const float* key_  = (const float*)d_in[1];
    const float* value = (const float*)d_in[2];
    const float* mask  = (const float*)d_in[3];
    const float* Wq = (const float*)d_in[4];
    const float* bq = (const float*)d_in[5];
    const float* Wk = (const float*)d_in[6];
    const float* bk = (const float*)d_in[7];
    const float* Wv = (const float*)d_in[8];
    const float* bv = (const float*)d_in[9];
    const float* Wc = (const float*)d_in[10];
    const float* bc = (const float*)d_in[11];
    const float* rms1 = (const float*)d_in[12];
    const float* w1 = (const float*)d_in[13];
    const float* b1 = (const float*)d_in[14];
    const float* w2 = (const float*)d_in[15];
    const float* b2 = (const float*)d_in[16];
    const float* rms2 = (const float*)d_in[17];
    float* out = (float*)d_out;

    float *Qp, *Kp, *Vp, *Op, *Tp, *Rp, *Hp;
    cudaGetSymbolAddress((void**)&Qp, g_Q);
    cudaGetSymbolAddress((void**)&Kp, g_K);
    cudaGetSymbolAddress((void**)&Vp, g_V);
    cudaGetSymbolAddress((void**)&Op, g_O);
    cudaGetSymbolAddress((void**)&Tp, g_T);
    cudaGetSymbolAddress((void**)&Rp, g_R);
    cudaGetSymbolAddress((void**)&Hp, g_Hm);

    cudaFuncSetAttribute(attn_kernel,
                         cudaFuncAttributeMaxDynamicSharedMemorySize, ATTN_SMEM);

    dim3 blk(256);

    // QKV projections
    sgemm_bias<0><<<dim3(8, 32), blk>>>(query, Wq, bq, Qp, MTOT, DD, DD);
    sgemm_bias<0><<<dim3(8, 32), blk>>>(key_,  Wk, bk, Kp, MTOT, DD, DD);
    sgemm_bias<0><<<dim3(8, 32), blk>>>(value, Wv, bv, Vp, MTOT, DD, DD);

    // Fused attention
    attn_kernel<<<dim3(SS / 64, HH, BB), blk, ATTN_SMEM>>>(Qp, Kp, Vp, mask, Op);

    // Output projection
    sgemm_bias<0><<<dim3(8, 32), blk>>>(Op, Wc, bc, Tp, MTOT, DD, DD);

    // RMSNorm 1 (attn_out + query)
    add_rmsnorm<<<MTOT, 256>>>(Tp, query, rms1, Rp);

    // MLP
    sgemm_bias<1><<<dim3(4, 32), blk>>>(Rp, w1, b1, Hp, MTOT, DD / 2, DD);
    sgemm_bias<0><<<dim3(8, 32), blk>>>(Hp, w2, b2, Tp, MTOT, DD, DD / 2);

    // RMSNorm 2 (rms + mlp_out) -> final output
    add_rmsnorm<<<MTOT, 256>>>(Rp, Tp, rms2, out);
}

// round 2
// speedup vs baseline: 2.7990x; 2.7990x over previous
#include <cuda_runtime.h>
#include <cuda_bf16.h>
#include <math.h>
#include <stdint.h>

// Problem constants
#define BB 2
#define SS 2048
#define DD 1024
#define HH 16
#define MTOT (BB*SS)          // 4096 rows

// ---------------------------------------------------------------------------
// Scratch (device globals; no allocation allowed)
// ---------------------------------------------------------------------------
__device__ __align__(256) __nv_bfloat16 g_WqkvTh[3072*1024];
__device__ __align__(256) __nv_bfloat16 g_WqkvTl[3072*1024];
__device__ __align__(256) __nv_bfloat16 g_WcTh[1024*1024];
__device__ __align__(256) __nv_bfloat16 g_WcTl[1024*1024];
__device__ __align__(256) __nv_bfloat16 g_W1Th[512*1024];
__device__ __align__(256) __nv_bfloat16 g_W1Tl[512*1024];
__device__ __align__(256) __nv_bfloat16 g_W2Th[1024*512];
__device__ __align__(256) __nv_bfloat16 g_W2Tl[1024*512];
__device__ __align__(256) float g_bias3[3072];

__device__ __align__(256) __nv_bfloat16 g_Ah[MTOT*1024];
__device__ __align__(256) __nv_bfloat16 g_Al[MTOT*1024];

__device__ __align__(256) float g_QKV[MTOT*3072];
__device__ __align__(256) __nv_bfloat16 g_Qh[BB*HH*SS*64];
__device__ __align__(256) __nv_bfloat16 g_Ql[BB*HH*SS*64];
__device__ __align__(256) __nv_bfloat16 g_Kh[BB*HH*SS*64];
__device__ __align__(256) __nv_bfloat16 g_Kl[BB*HH*SS*64];
__device__ __align__(256) __nv_bfloat16 g_Vh[BB*HH*64*SS];
__device__ __align__(256) __nv_bfloat16 g_Vl[BB*HH*64*SS];

__device__ __align__(256) float g_O[MTOT*1024];
__device__ __align__(256) float g_T[MTOT*1024];
__device__ __align__(256) float g_R[MTOT*1024];
__device__ __align__(256) float g_Hm[MTOT*512];

// ---------------------------------------------------------------------------
// Helpers
// ---------------------------------------------------------------------------
#define CP16(dst,src) asm volatile("cp.async.cg.shared.global [%0], [%1], 16;\n" :: "r"(dst), "l"(src))
#define CP_COMMIT()   asm volatile("cp.async.commit_group;\n")
#define CP_WAIT(n)    asm volatile("cp.async.wait_group %0;\n" :: "n"(n))

// swizzled byte offsets into bf16 tiles
// 32-wide (64B rows): chunk xor (row>>1)&3
#define OFF32(row,k) (((row)<<6) + ((((k)>>3) ^ (((row)>>1)&3))<<4) + (((k)&7)<<1))
// 64-wide (128B rows): chunk xor row&7
#define OFF64(row,k) (((row)<<7) + ((((k)>>3) ^ ((row)&7))<<4) + (((k)&7)<<1))

__device__ __forceinline__ uint32_t smaddr(const void* p){
    return (uint32_t)__cvta_generic_to_shared(p);
}

__device__ __forceinline__ void mma_bf16(float* c, const uint32_t* a, uint32_t b0, uint32_t b1){
    asm volatile("mma.sync.aligned.m16n8k16.row.col.f32.bf16.bf16.f32 "
        "{%0,%1,%2,%3},{%4,%5,%6,%7},{%8,%9},{%0,%1,%2,%3};\n"
        : "+f"(c[0]),"+f"(c[1]),"+f"(c[2]),"+f"(c[3])
        : "r"(a[0]),"r"(a[1]),"r"(a[2]),"r"(a[3]),"r"(b0),"r"(b1));
}

__device__ __forceinline__ uint32_t packbf(float x, float y){
    __nv_bfloat162 t = __floats2bfloat162_rn(x, y);
    return *reinterpret_cast<uint32_t*>(&t);
}

__device__ __forceinline__ void split2(float x, __nv_bfloat16& h, __nv_bfloat16& l){
    h = __float2bfloat16_rn(x);
    l = __float2bfloat16_rn(x - __bfloat162float(h));
}

// ---------------------------------------------------------------------------
// Weight transpose + split: in [K][N] fp32 -> outh/outl [N][K] bf16
// grid (N/32, K/32), block (32, 8)
// ---------------------------------------------------------------------------
__global__ void transpose_split(const float* __restrict__ in,
                                __nv_bfloat16* __restrict__ outh,
                                __nv_bfloat16* __restrict__ outl, int K, int N)
{
    __shared__ float t[32][33];
    const int n0 = blockIdx.x*32, k0 = blockIdx.y*32;
    const int tx = threadIdx.x, ty = threadIdx.y;
    #pragma unroll
    for (int r = 0; r < 4; r++)
        t[ty + r*8][tx] = in[(size_t)(k0 + ty + r*8)*N + n0 + tx];
    __syncthreads();
    #pragma unroll
    for (int r = 0; r < 4; r++){
        int nl = ty + r*8;
        float v = t[tx][nl];
        __nv_bfloat16 h, l; split2(v, h, l);
        size_t o = (size_t)(n0 + nl)*K + k0 + tx;
        outh[o] = h; outl[o] = l;
    }
}

// ---------------------------------------------------------------------------
// Plain split: in [n] fp32 -> h/l bf16 (vectorized by 4)
// ---------------------------------------------------------------------------
__global__ void split_plain(const float* __restrict__ in,
                            __nv_bfloat16* __restrict__ oh,
                            __nv_bfloat16* __restrict__ ol, int n4)
{
    int i = blockIdx.x*256 + threadIdx.x;
    if (i >= n4) return;
    float4 v = ((const float4*)in)[i];
    __nv_bfloat16 h0,h1,h2,h3,l0,l1,l2,l3;
    split2(v.x,h0,l0); split2(v.y,h1,l1); split2(v.z,h2,l2); split2(v.w,h3,l3);
    uint2 hh, ll;
    hh.x = ((uint32_t)*(uint16_t*)&h1 << 16) | *(uint16_t*)&h0;
    hh.y = ((uint32_t)*(uint16_t*)&h3 << 16) | *(uint16_t*)&h2;
    ll.x = ((uint32_t)*(uint16_t*)&l1 << 16) | *(uint16_t*)&l0;
    ll.y = ((uint32_t)*(uint16_t*)&l3 << 16) | *(uint16_t*)&l2;
    ((uint2*)oh)[i] = hh;
    ((uint2*)ol)[i] = ll;
}

__global__ void concat_bias(const float* a, const float* b, const float* c, float* out){
    int i = blockIdx.x*256 + threadIdx.x;
    if (i >= 3072) return;
    out[i] = (i < 1024) ? a[i] : ((i < 2048) ? b[i-1024] : c[i-2048]);
}

// ---------------------------------------------------------------------------
// Q/K head split: QKV [M][3072] -> Qh/Ql/Kh/Kl [B*H][S][64] (Q scaled 1/32)
// grid 4096 x 256 threads
// ---------------------------------------------------------------------------
__global__ void qk_head_split(const float* __restrict__ QKV,
                              __nv_bfloat16* __restrict__ Qh, __nv_bfloat16* __restrict__ Ql,
                              __nv_bfloat16* __restrict__ Kh, __nv_bfloat16* __restrict__ Kl)
{
    int idx = blockIdx.x*256 + threadIdx.x;     // m(12b) h(4b) d4(4b)
    int m = idx >> 8; int rest = idx & 255; int h = rest >> 4; int d4 = rest & 15;
    int b = m >> 11; int s = m & 2047;
    float4 qv = *(const float4*)(QKV + (size_t)m*3072 + h*64 + d4*4);
    float4 kv = *(const float4*)(QKV + (size_t)m*3072 + 1024 + h*64 + d4*4);
    const float sc = 0.03125f;
    size_t o = (((size_t)(b*HH + h))*SS + s)*64 + d4*4;
    __nv_bfloat16 h0,h1,h2,h3,l0,l1,l2,l3;
    split2(qv.x*sc,h0,l0); split2(qv.y*sc,h1,l1); split2(qv.z*sc,h2,l2); split2(qv.w*sc,h3,l3);
    uint2 u;
    u.x = ((uint32_t)*(uint16_t*)&h1<<16)|*(uint16_t*)&h0; u.y = ((uint32_t)*(uint16_t*)&h3<<16)|*(uint16_t*)&h2;
    *(uint2*)(Qh + o) = u;
    u.x = ((uint32_t)*(uint16_t*)&l1<<16)|*(uint16_t*)&l0; u.y = ((uint32_t)*(uint16_t*)&l3<<16)|*(uint16_t*)&l2;
    *(uint2*)(Ql + o) = u;
    split2(kv.x,h0,l0); split2(kv.y,h1,l1); split2(kv.z,h2,l2); split2(kv.w,h3,l3);
    u.x = ((uint32_t)*(uint16_t*)&h1<<16)|*(uint16_t*)&h0; u.y = ((uint32_t)*(uint16_t*)&h3<<16)|*(uint16_t*)&h2;
    *(uint2*)(Kh + o) = u;
    u.x = ((uint32_t)*(uint16_t*)&l1<<16)|*(uint16_t*)&l0; u.y = ((uint32_t)*(uint16_t*)&l3<<16)|*(uint16_t*)&l2;
    *(uint2*)(Kl + o) = u;
}

// ---------------------------------------------------------------------------
// V transpose + split: QKV V-section [S][64] per (b,h) -> Vh/Vl [B*H][64][S]
// grid (S/32, 2, B*H), block (32,8)
// ---------------------------------------------------------------------------
__global__ void v_transpose_split(const float* __restrict__ QKV,
                                  __nv_bfloat16* __restrict__ Vh,
                                  __nv_bfloat16* __restrict__ Vl)
{
    __shared__ float t[32][33];
    const int bh = blockIdx.z;
    const int s0 = blockIdx.x*32, d0 = blockIdx.y*32;
    const int b = bh >> 4, h = bh & 15;
    const int tx = threadIdx.x, ty = threadIdx.y;
    #pragma unroll
    for (int r = 0; r < 4; r++)
        t[ty + r*8][tx] = QKV[(size_t)(b*SS + s0 + ty + r*8)*3072 + 2048 + h*64 + d0 + tx];
    __syncthreads();
    #pragma unroll
    for (int r = 0; r < 4; r++){
        int dl = ty + r*8;
        float v = t[tx][dl];
        __nv_bfloat16 hh, ll; split2(v, hh, ll);
        size_t o = ((size_t)bh*64 + d0 + dl)*SS + s0 + tx;
        Vh[o] = hh; Vl[o] = ll;
    }
}

// ---------------------------------------------------------------------------
// Split-bf16 TN GEMM: C[M,N] = A[M,K] @ B^T[N,K] + bias, optional ReLU.
// A as (Ah,Al) [M][K]; B as (Bh,Bl) [N][K] (pre-transposed weights).
// 128x128x32 tiles, 256 threads (8 warps as 2x4), mma m16n8k16, cp.async x2.
// ---------------------------------------------------------------------------
#define G_STAGE 32768

template<int RELU>
__global__ __launch_bounds__(256) void gemm_split(
    const __nv_bfloat16* __restrict__ Ah, const __nv_bfloat16* __restrict__ Al,
    const __nv_bfloat16* __restrict__ Bh, const __nv_bfloat16* __restrict__ Bl,
    const float* __restrict__ bias, float* __restrict__ C, int M, int N, int K)
{
    extern __shared__ char sm[];
    const int tid = threadIdx.x;
    const int wid = tid >> 5, lane = tid & 31;
    const int wm = wid >> 2, wn = wid & 3;
    const int r = lane >> 2, q = lane & 3;
    const int rowBase = blockIdx.y*128, colBase = blockIdx.x*128;

    // cp.async mapping: row = tid>>1, chunks {2*(tid&1), 2*(tid&1)+1}
    const int ldRow = tid >> 1;
    const int c0 = (tid & 1)*2;
    const int sw = (ldRow >> 1) & 3;
    const int rowoff = ldRow << 6;
    const uint32_t d0 = rowoff + (((c0  ) ^ sw) << 4);
    const uint32_t d1 = rowoff + (((c0+1) ^ sw) << 4);

    const __nv_bfloat16* srcs[4];
    srcs[0] = Ah + (size_t)(rowBase + ldRow)*K;
    srcs[1] = Al + (size_t)(rowBase + ldRow)*K;
    srcs[2] = Bh + (size_t)(colBase + ldRow)*K;
    srcs[3] = Bl + (size_t)(colBase + ldRow)*K;

    const uint32_t smbase = smaddr(sm);

    float acc[4][4][4];
    #pragma unroll
    for (int i=0;i<4;i++)
        #pragma unroll
        for (int j=0;j<4;j++)
            #pragma unroll
            for (int k=0;k<4;k++) acc[i][j][k] = 0.0f;

    const int KT = K >> 5;

    // issue stage st for k-offset k0
    #define G_ISSUE(st, k0) { \
        uint32_t sb = smbase + (st)*G_STAGE; \
        _Pragma("unroll") \
        for (int p = 0; p < 4; p++){ \
            const __nv_bfloat16* s = srcs[p] + (k0) + c0*8; \
            CP16(sb + p*8192 + d0, s); \
            CP16(sb + p*8192 + d1, s + 8); \
        } }

    G_ISSUE(0, 0); CP_COMMIT();
    G_ISSUE(1, 32); CP_COMMIT();
    CP_WAIT(1); __syncthreads();

    for (int kt = 0; kt < KT; kt++){
        const char* stg = sm + (kt & 1)*G_STAGE;
        const char* pAh = stg;
        const char* pAl = stg + 8192;
        const char* pBh = stg + 16384;
        const char* pBl = stg + 24576;
        #pragma unroll
        for (int ks = 0; ks < 2; ks++){
            uint32_t ah[4][4], al[4][4], bh[4][2], bl[4][2];
            const int kk = ks*16 + q*2;
            #pragma unroll
            for (int mt = 0; mt < 4; mt++){
                int row = wm*64 + mt*16 + r;
                ah[mt][0] = *(const uint32_t*)(pAh + OFF32(row,   kk));
                ah[mt][1] = *(const uint32_t*)(pAh + OFF32(row+8, kk));
                ah[mt][2] = *(const uint32_t*)(pAh + OFF32(row,   kk+8));
                ah[mt][3] = *(const uint32_t*)(pAh + OFF32(row+8, kk+8));
                al[mt][0] = *(const uint32_t*)(pAl + OFF32(row,   kk));
                al[mt][1] = *(const uint32_t*)(pAl + OFF32(row+8, kk));
                al[mt][2] = *(const uint32_t*)(pAl + OFF32(row,   kk+8));
                al[mt][3] = *(const uint32_t*)(pAl + OFF32(row+8, kk+8));
            }
            #pragma unroll
            for (int nt = 0; nt < 4; nt++){
                int rowb = wn*32 + nt*8 + r;
                bh[nt][0] = *(const uint32_t*)(pBh + OFF32(rowb, kk));
                bh[nt][1] = *(const uint32_t*)(pBh + OFF32(rowb, kk+8));
                bl[nt][0] = *(const uint32_t*)(pBl + OFF32(rowb, kk));
                bl[nt][1] = *(const uint32_t*)(pBl + OFF32(rowb, kk+8));
            }
            #pragma unroll
            for (int mt = 0; mt < 4; mt++)
                #pragma unroll
                for (int nt = 0; nt < 4; nt++){
                    mma_bf16(acc[mt][nt], ah[mt], bh[nt][0], bh[nt][1]);
                    mma_bf16(acc[mt][nt], ah[mt], bl[nt][0], bl[nt][1]);
                    mma_bf16(acc[mt][nt], al[mt], bh[nt][0], bh[nt][1]);
                }
        }
        __syncthreads();
        if (kt + 2 < KT){
            G_ISSUE(kt & 1, (kt+2)*32); CP_COMMIT(); CP_WAIT(1);
        } else {
            CP_WAIT(0);
        }
        __syncthreads();
    }
    #undef G_ISSUE

    // Epilogue
    #pragma unroll
    for (int mt = 0; mt < 4; mt++){
        int row0 = rowBase + wm*64 + mt*16 + r;
        #pragma unroll
        for (int nt = 0; nt < 4; nt++){
            int col = colBase + wn*32 + nt*8 + q*2;
            float b0 = bias[col], b1 = bias[col+1];
            float v0 = acc[mt][nt][0] + b0, v1 = acc[mt][nt][1] + b1;
            float v2 = acc[mt][nt][2] + b0, v3 = acc[mt][nt][3] + b1;
            if (RELU){ v0=fmaxf(v0,0.f); v1=fmaxf(v1,0.f); v2=fmaxf(v2,0.f); v3=fmaxf(v3,0.f); }
            float2 p0 = {v0, v1}, p1 = {v2, v3};
            *(float2*)(C + (size_t)row0*N + col) = p0;
            *(float2*)(C + (size_t)(row0+8)*N + col) = p1;
        }
    }
}

// ---------------------------------------------------------------------------
// Flash attention, split-bf16 mma. Grid (S/64, H, B), 128 threads (4 warps).
// Each warp owns 16 q-rows; P kept in registers (C->A fragment repack).
// Q/K layout [B*H][S][64]; V layout [B*H][64][S]; out fp32 [M][1024].
// ---------------------------------------------------------------------------
#define A_STAGE 33024        // Kh 8K | Kl 8K | Vh 8K | Vl 8K | mask 256B
#define A_SMEM  (2*A_STAGE + 16384)

__global__ __launch_bounds__(128) void attn_mma(
    const __nv_bfloat16* __restrict__ Qh, const __nv_bfloat16* __restrict__ Ql,
    const __nv_bfloat16* __restrict__ Kh, const __nv_bfloat16* __restrict__ Kl,
    const __nv_bfloat16* __restrict__ Vh, const __nv_bfloat16* __restrict__ Vl,
    const float* __restrict__ mask, float* __restrict__ O)
{
    extern __shared__ char sm[];
    const int tid = threadIdx.x;
    const int wid = tid >> 5, lane = tid & 31;
    const int r = lane >> 2, q = lane & 3;
    const int b = blockIdx.z, h = blockIdx.y;
    const int bh = b*HH + h;
    const int q0 = blockIdx.x*64;

    const uint32_t smbase = smaddr(sm);
    const uint32_t QH_OFF = 2*A_STAGE, QL_OFF = 2*A_STAGE + 8192;

    // cp.async mapping for 64x64 tiles: row = tid>>1, chunks {(tid&1)*4 .. +3}
    const int ldRow = tid >> 1;
    const int cb = (tid & 1)*4;

    const __nv_bfloat16* kh_g = Kh + ((size_t)bh*SS)*64;
    const __nv_bfloat16* kl_g = Kl + ((size_t)bh*SS)*64;
    const __nv_bfloat16* vh_g = Vh + ((size_t)bh*64)*SS;
    const __nv_bfloat16* vl_g = Vl + ((size_t)bh*64)*SS;
    const float* mk_g = mask + b*SS;

    #define A_ISSUE(st, k0) { \
        uint32_t sb = smbase + (st)*A_STAGE; \
        _Pragma("unroll") \
        for (int c = 0; c < 4; c++){ \
            int ch = cb + c; \
            uint32_t doff = (ldRow<<7) + ((ch ^ (ldRow&7))<<4); \
            CP16(sb + doff,         kh_g + (size_t)((k0) + ldRow)*64 + ch*8); \
            CP16(sb + 8192 + doff,  kl_g + (size_t)((k0) + ldRow)*64 + ch*8); \
            CP16(sb + 16384 + doff, vh_g + (size_t)ldRow*SS + (k0) + ch*8); \
            CP16(sb + 24576 + doff, vl_g + (size_t)ldRow*SS + (k0) + ch*8); \
        } \
        if (tid < 16) CP16(sb + 32768 + tid*16, mk_g + (k0) + tid*4); }

    // prologue: Q + stage0, then stage1
    {
        const __nv_bfloat16* qh_g = Qh + ((size_t)bh*SS + q0)*64;
        const __nv_bfloat16* ql_g = Ql + ((size_t)bh*SS + q0)*64;
        #pragma unroll
        for (int c = 0; c < 4; c++){
            int ch = cb + c;
            uint32_t doff = (ldRow<<7) + ((ch ^ (ldRow&7))<<4);
            CP16(smbase + QH_OFF + doff, qh_g + (size_t)ldRow*64 + ch*8);
            CP16(smbase + QL_OFF + doff, ql_g + (size_t)ldRow*64 + ch*8);
        }
        A_ISSUE(0, 0); CP_COMMIT();
        A_ISSUE(1, 64); CP_COMMIT();
        CP_WAIT(1); __syncthreads();
    }

    // preload Q fragments
    uint32_t qfh[4][4], qfl[4][4];
    {
        const char* pQh = sm + QH_OFF;
        const char* pQl = sm + QL_OFF;
        #pragma unroll
        for (int ks = 0; ks < 4; ks++){
            int row = wid*16 + r;
            int kk = ks*16 + q*2;
            qfh[ks][0] = *(const uint32_t*)(pQh + OFF64(row,   kk));
            qfh[ks][1] = *(const uint32_t*)(pQh + OFF64(row+8, kk));
            qfh[ks][2] = *(const uint32_t*)(pQh + OFF64(row,   kk+8));
            qfh[ks][3] = *(const uint32_t*)(pQh + OFF64(row+8, kk+8));
            qfl[ks][0] = *(const uint32_t*)(pQl + OFF64(row,   kk));
            qfl[ks][1] = *(const uint32_t*)(pQl + OFF64(row+8, kk));
            qfl[ks][2] = *(const uint32_t*)(pQl + OFF64(row,   kk+8));
            qfl[ks][3] = *(const uint32_t*)(pQl + OFF64(row+8, kk+8));
        }
    }

    float o[8][4];
    #pragma unroll
    for (int i=0;i<8;i++){ o[i][0]=0.f; o[i][1]=0.f; o[i][2]=0.f; o[i][3]=0.f; }
    float m0 = -INFINITY, m1 = -INFINITY, l0 = 0.f, l1 = 0.f;

    const int KT = SS/64;
    for (int kt = 0; kt < KT; kt++){
        const char* stg = sm + (kt & 1)*A_STAGE;
        const char* pKh = stg;
        const char* pKl = stg + 8192;
        const char* pVh = stg + 16384;
        const char* pVl = stg + 24576;
        const float* mk = (const float*)(stg + 32768);

        // ---- S = Q @ K^T ----
        float s[8][4];
        #pragma unroll
        for (int i=0;i<8;i++){ s[i][0]=0.f; s[i][1]=0.f; s[i][2]=0.f; s[i][3]=0.f; }

        #pragma unroll
        for (int ks = 0; ks < 4; ks++){
            const int kk = ks*16 + q*2;
            #pragma unroll
            for (int nt = 0; nt < 8; nt++){
                int rowb = nt*8 + r;
                uint32_t kb0 = *(const uint32_t*)(pKh + OFF64(rowb, kk));
                uint32_t kb1 = *(const uint32_t*)(pKh + OFF64(rowb, kk+8));
                uint32_t kl0 = *(const uint32_t*)(pKl + OFF64(rowb, kk));
                uint32_t kl1 = *(const uint32_t*)(pKl + OFF64(rowb, kk+8));
                mma_bf16(s[nt], qfh[ks], kb0, kb1);
                mma_bf16(s[nt], qfh[ks], kl0, kl1);
                mma_bf16(s[nt], qfl[ks], kb0, kb1);
            }
        }

        // ---- mask + online softmax ----
        float mx0 = -INFINITY, mx1 = -INFINITY;
        #pragma unroll
        for (int nt = 0; nt < 8; nt++){
            float2 mv = *(const float2*)(mk + nt*8 + q*2);
            float a0 = (mv.x - 1.0f)*1e12f, a1 = (mv.y - 1.0f)*1e12f;
            s[nt][0] += a0; s[nt][1] += a1; s[nt][2] += a0; s[nt][3] += a1;
            mx0 = fmaxf(mx0, fmaxf(s[nt][0], s[nt][1]));
            mx1 = fmaxf(mx1, fmaxf(s[nt][2], s[nt][3]));
        }
        mx0 = fmaxf(mx0, __shfl_xor_sync(0xffffffffu, mx0, 1));
        mx0 = fmaxf(mx0, __shfl_xor_sync(0xffffffffu, mx0, 2));
        mx1 = fmaxf(mx1, __shfl_xor_sync(0xffffffffu, mx1, 1));
        mx1 = fmaxf(mx1, __shfl_xor_sync(0xffffffffu, mx1, 2));
        float mn0 = fmaxf(m0, mx0), mn1 = fmaxf(m1, mx1);
        float cr0 = __expf(m0 - mn0), cr1 = __expf(m1 - mn1);
        m0 = mn0; m1 = mn1;
        float sum0 = 0.f, sum1 = 0.f;
        #pragma unroll
        for (int nt = 0; nt < 8; nt++){
            s[nt][0] = __expf(s[nt][0] - mn0);
            s[nt][1] = __expf(s[nt][1] - mn0);
            s[nt][2] = __expf(s[nt][2] - mn1);
            s[nt][3] = __expf(s[nt][3] - mn1);
            sum0 += s[nt][0] + s[nt][1];
            sum1 += s[nt][2] + s[nt][3];
        }
        sum0 += __shfl_xor_sync(0xffffffffu, sum0, 1);
        sum0 += __shfl_xor_sync(0xffffffffu, sum0, 2);
        sum1 += __shfl_xor_sync(0xffffffffu, sum1, 1);
        sum1 += __shfl_xor_sync(0xffffffffu, sum1, 2);
        l0 = l0*cr0 + sum0; l1 = l1*cr1 + sum1;
        #pragma unroll
        for (int nt = 0; nt < 8; nt++){
            o[nt][0] *= cr0; o[nt][1] *= cr0; o[nt][2] *= cr1; o[nt][3] *= cr1;
        }

        // ---- O += P @ V (P repacked from S fragments in registers) ----
        #pragma unroll
        for (int j = 0; j < 4; j++){
            uint32_t ph[4], pl[4];
            ph[0] = packbf(s[2*j][0],   s[2*j][1]);
            ph[1] = packbf(s[2*j][2],   s[2*j][3]);
            ph[2] = packbf(s[2*j+1][0], s[2*j+1][1]);
            ph[3] = packbf(s[2*j+1][2], s[2*j+1][3]);
            {
                __nv_bfloat162 t0 = *(__nv_bfloat162*)&ph[0];
                __nv_bfloat162 t1 = *(__nv_bfloat162*)&ph[1];
                __nv_bfloat162 t2 = *(__nv_bfloat162*)&ph[2];
                __nv_bfloat162 t3 = *(__nv_bfloat162*)&ph[3];
                pl[0] = packbf(s[2*j][0]  -__bfloat162float(t0.x), s[2*j][1]  -__bfloat162float(t0.y));
                pl[1] = packbf(s[2*j][2]  -__bfloat162float(t1.x), s[2*j][3]  -__bfloat162float(t1.y));
                pl[2] = packbf(s[2*j+1][0]-__bfloat162float(t2.x), s[2*j+1][1]-__bfloat162float(t2.y));
                pl[3] = packbf(s[2*j+1][2]-__bfloat162float(t3.x), s[2*j+1][3]-__bfloat162float(t3.y));
            }
            const int kk = j*16 + q*2;
            #pragma unroll
            for (int nt = 0; nt < 8; nt++){
                int rowv = nt*8 + r;
                uint32_t vb0 = *(const uint32_t*)(pVh + OFF64(rowv, kk));
                uint32_t vb1 = *(const uint32_t*)(pVh + OFF64(rowv, kk+8));
                uint32_t vl0 = *(const uint32_t*)(pVl + OFF64(rowv, kk));
                uint32_t vl1 = *(const uint32_t*)(pVl + OFF64(rowv, kk+8));
                mma_bf16(o[nt], ph, vb0, vb1);
                mma_bf16(o[nt], ph, vl0, vl1);
                mma_bf16(o[nt], pl, vb0, vb1);
            }
        }

        __syncthreads();
        if (kt + 2 < KT){
            A_ISSUE(kt & 1, (kt+2)*64); CP_COMMIT(); CP_WAIT(1);
        } else {
            CP_WAIT(0);
        }
        __syncthreads();
    }
    #undef A_ISSUE

    // ---- write O ----
    float inv0 = 1.0f/l0, inv1 = 1.0f/l1;
    int mrow = q0 + wid*16 + r;
    float* Og = O + ((size_t)(b*SS) + mrow)*DD + h*64;
    #pragma unroll
    for (int nt = 0; nt < 8; nt++){
        int col = nt*8 + q*2;
        float2 v0 = {o[nt][0]*inv0, o[nt][1]*inv0};
        float2 v1 = {o[nt][2]*inv1, o[nt][3]*inv1};
        *(float2*)(Og + col) = v0;
        *(float2*)(Og + (size_t)8*DD + col) = v1;
    }
}

// ---------------------------------------------------------------------------
// Residual add + RMSNorm (unchanged from R1)
// ---------------------------------------------------------------------------
__global__ __launch_bounds__(256) void add_rmsnorm(
    const float* __restrict__ a, const float* __restrict__ b,
    const float* __restrict__ gamma, float* __restrict__ out)
{
    const int row = blockIdx.x;
    const int t = threadIdx.x;
    const float4* pa = (const float4*)(a + (size_t)row * DD);
    const float4* pb = (const float4*)(b + (size_t)row * DD);
    float4 xa = pa[t], xb = pb[t];
    float4 x;
    x.x = xa.x + xb.x; x.y = xa.y + xb.y; x.z = xa.z + xb.z; x.w = xa.w + xb.w;
    float ss = x.x*x.x + x.y*x.y + x.z*x.z + x.w*x.w;
    #pragma unroll
    for (int o = 16; o >= 1; o >>= 1)
        ss += __shfl_xor_sync(0xffffffffu, ss, o);
    __shared__ float red[8];
    if ((t & 31) == 0) red[t >> 5] = ss;
    __syncthreads();
    float tot = red[0]+red[1]+red[2]+red[3]+red[4]+red[5]+red[6]+red[7];
    float rms = sqrtf(tot * (1.0f / 1024.0f));
    float inv = 1.0f / (rms + 1e-8f);
    float4 gv = ((const float4*)gamma)[t];
    float4 o;
    o.x = gv.x*x.x*inv; o.y = gv.y*x.y*inv; o.z = gv.z*x.z*inv; o.w = gv.w*x.w*inv;
    ((float4*)(out + (size_t)row * DD))[t] = o;
}

// ---------------------------------------------------------------------------
// Launch
// ---------------------------------------------------------------------------
extern "C" void kernel_launch(void* const* d_in, const int* in_sizes, int n_in,
                              void* d_out, int out_size)
{
    const float* query = (const float*)d_in[0];
    const float* key_  = (const float*)d_in[1];
    const float* value = (const float*)d_in[2];
    const float* mask  = (const float*)d_in[3];
    const float* Wq = (const float*)d_in[4];
    const float* bq = (const float*)d_in[5];
    const float* Wk = (const float*)d_in[6];
    const float* bk = (const float*)d_in[7];
    const float* Wv = (const float*)d_in[8];
    const float* bv = (const float*)d_in[9];
    const float* Wc = (const float*)d_in[10];
    const float* bc = (const float*)d_in[11];
    const float* rms1 = (const float*)d_in[12];
    const float* w1 = (const float*)d_in[13];
    const float* b1 = (const float*)d_in[14];
    const float* w2 = (const float*)d_in[15];
    const float* b2 = (const float*)d_in[16];
    const float* rms2 = (const float*)d_in[17];
    float* out = (float*)d_out;

    // NOTE: qkv projection reads from K input "key_" and "value" separately.
    // Reference: q = query@Wq, k = key@Wk, v = value@Wv. Inputs differ, so we
    // need splits of query, key, value activations. query/key/value are all
    // [M][1024]; we run three GEMMs against the combined weight? No — A differs.
    // So: QKV combined GEMM is only valid if A is the same. It isn't. We instead
    // run three GEMMs, each writing its section of g_QKV.

    __nv_bfloat16 *WqkvTh, *WqkvTl, *WcTh, *WcTl, *W1Th, *W1Tl, *W2Th, *W2Tl;
    __nv_bfloat16 *Ahp, *Alp, *Qhp, *Qlp, *Khp, *Klp, *Vhp, *Vlp;
    float *bias3, *QKV, *Op, *Tp, *Rp, *Hmp;
    cudaGetSymbolAddress((void**)&WqkvTh, g_WqkvTh);
    cudaGetSymbolAddress((void**)&WqkvTl, g_WqkvTl);
    cudaGetSymbolAddress((void**)&WcTh, g_WcTh);
    cudaGetSymbolAddress((void**)&WcTl, g_WcTl);
    cudaGetSymbolAddress((void**)&W1Th, g_W1Th);
    cudaGetSymbolAddress((void**)&W1Tl, g_W1Tl);
    cudaGetSymbolAddress((void**)&W2Th, g_W2Th);
    cudaGetSymbolAddress((void**)&W2Tl, g_W2Tl);
    cudaGetSymbolAddress((void**)&bias3, g_bias3);
    cudaGetSymbolAddress((void**)&Ahp, g_Ah);
    cudaGetSymbolAddress((void**)&Alp, g_Al);
    cudaGetSymbolAddress((void**)&QKV, g_QKV);
    cudaGetSymbolAddress((void**)&Qhp, g_Qh);
    cudaGetSymbolAddress((void**)&Qlp, g_Ql);
    cudaGetSymbolAddress((void**)&Khp, g_Kh);
    cudaGetSymbolAddress((void**)&Klp, g_Kl);
    cudaGetSymbolAddress((void**)&Vhp, g_Vh);
    cudaGetSymbolAddress((void**)&Vlp, g_Vl);
    cudaGetSymbolAddress((void**)&Op, g_O);
    cudaGetSymbolAddress((void**)&Tp, g_T);
    cudaGetSymbolAddress((void**)&Rp, g_R);
    cudaGetSymbolAddress((void**)&Hmp, g_Hm);

    cudaFuncSetAttribute(gemm_split<0>, cudaFuncAttributeMaxDynamicSharedMemorySize, 2*G_STAGE);
    cudaFuncSetAttribute(gemm_split<1>, cudaFuncAttributeMaxDynamicSharedMemorySize, 2*G_STAGE);
    cudaFuncSetAttribute(attn_mma, cudaFuncAttributeMaxDynamicSharedMemorySize, A_SMEM);

    dim3 tb(32, 8);

    // Weight prep (transpose + split)
    transpose_split<<<dim3(32,32), tb>>>(Wq, WqkvTh,              WqkvTl,              1024, 1024);
    transpose_split<<<dim3(32,32), tb>>>(Wk, WqkvTh + 1024*1024,  WqkvTl + 1024*1024,  1024, 1024);
    transpose_split<<<dim3(32,32), tb>>>(Wv, WqkvTh + 2048*1024,  WqkvTl + 2048*1024,  1024, 1024);
    transpose_split<<<dim3(32,32), tb>>>(Wc, WcTh, WcTl, 1024, 1024);
    transpose_split<<<dim3(16,32), tb>>>(w1, W1Th, W1Tl, 1024, 512);
    transpose_split<<<dim3(32,16), tb>>>(w2, W2Th, W2Tl, 512, 1024);
    concat_bias<<<12, 256>>>(bq, bk, bv, bias3);

    // Q/K/V projections (separate A inputs -> three GEMMs into g_QKV sections)
    split_plain<<<4096, 256>>>(query, Ahp, Alp, MTOT*1024/4);
    gemm_split<0><<<dim3(8,32), 256, 2*G_STAGE>>>(Ahp, Alp, WqkvTh, WqkvTl, bias3, QKV, MTOT, 3072, 1024);
    split_plain<<<4096, 256>>>(key_, Ahp, Alp, MTOT*1024/4);
    gemm_split<0><<<dim3(8,32), 256, 2*G_STAGE>>>(Ahp, Alp, WqkvTh + 1024*1024, WqkvTl + 1024*1024, bias3 + 1024, QKV + 1024, MTOT, 3072, 1024);
    split_plain<<<4096, 256>>>(value, Ahp, Alp, MTOT*1024/4);
    gemm_split<0><<<dim3(8,32), 256, 2*G_STAGE>>>(Ahp, Alp, WqkvTh + 2048*1024, WqkvTl + 2048*1024, bias3 + 2048, QKV + 2048, MTOT, 3072, 1024);

    // Head split + V transpose
    qk_head_split<<<4096, 256>>>(QKV, Qhp, Qlp, Khp, Klp);
    v_transpose_split<<<dim3(64, 2, 32), tb>>>(QKV, Vhp, Vlp);

    // Attention
    attn_mma<<<dim3(SS/64, HH, BB), 128, A_SMEM>>>(Qhp, Qlp, Khp, Klp, Vhp, Vlp, mask, Op);

    // Output projection
    split_plain<<<4096, 256>>>(Op, Ahp, Alp, MTOT*1024/4);
    gemm_split<0><<<dim3(8,32), 256, 2*G_STAGE>>>(Ahp, Alp, WcTh, WcTl, bc, Tp, MTOT, 1024, 1024);

    // RMSNorm 1
    add_rmsnorm<<<MTOT, 256>>>(Tp, query, rms1, Rp);

    // MLP
    split_plain<<<4096, 256>>>(Rp, Ahp, Alp, MTOT*1024/4);
    gemm_split<1><<<dim3(4,32), 256, 2*G_STAGE>>>(Ahp, Alp, W1Th, W1Tl, b1, Hmp, MTOT, 512, 1024);
    split_plain<<<2048, 256>>>(Hmp, Ahp, Alp, MTOT*512/4);
    gemm_split<0><<<dim3(8,32), 256, 2*G_STAGE>>>(Ahp, Alp, W2Th, W2Tl, b2, Tp, MTOT, 1024, 512);

    // RMSNorm 2 -> output
    add_rmsnorm<<<MTOT, 256>>>(Rp, Tp, rms2, out);
}